// round 6
// baseline (speedup 1.0000x reference)
#include <cuda_runtime.h>
#include <cuda_bf16.h>
#include <cstdint>
#include <math.h>

#define T_SEQ 2048
#define D_EMB 4096
#define QKV_N 6144
#define NH 32
#define DH 128
#define NG 8

// ---------------------------------------------------------------------------
// Scratch (__device__ globals; no cudaMalloc allowed)
// ---------------------------------------------------------------------------
__device__ float g_qkv[T_SEQ * QKV_N];              // fp32 QKV (gemm1 out)
__device__ __nv_bfloat16 g_qkvh[T_SEQ * QKV_N];     // roped+split QKV hi
__device__ __nv_bfloat16 g_qkvl[T_SEQ * QKV_N];     // roped+split QKV lo
__device__ __nv_bfloat16 g_ahi[T_SEQ * D_EMB];      // x split / y split hi
__device__ __nv_bfloat16 g_alo[T_SEQ * D_EMB];      // x split / y split lo
__device__ __nv_bfloat16 g_whi[QKV_N * D_EMB];      // W split hi
__device__ __nv_bfloat16 g_wlo[QKV_N * D_EMB];      // W split lo

// ---------------------------------------------------------------------------
// helpers
// ---------------------------------------------------------------------------
__device__ __forceinline__ uint32_t smem_u32(const void* p) {
    uint32_t a;
    asm("{ .reg .u64 t; cvta.to.shared.u64 t, %1; cvt.u32.u64 %0, t; }"
        : "=r"(a) : "l"(p));
    return a;
}
__device__ __forceinline__ void cp_async16(uint32_t dst, const void* src) {
    asm volatile("cp.async.cg.shared.global [%0], [%1], 16;"
                 :: "r"(dst), "l"(src));
}
__device__ __forceinline__ void cp_commit() {
    asm volatile("cp.async.commit_group;");
}
template <int N>
__device__ __forceinline__ void cp_wait() {
    asm volatile("cp.async.wait_group %0;" :: "n"(N));
}
__device__ __forceinline__ void ldsm_x4(uint32_t* r, uint32_t addr) {
    asm volatile("ldmatrix.sync.aligned.m8n8.x4.shared.b16 {%0,%1,%2,%3}, [%4];"
                 : "=r"(r[0]), "=r"(r[1]), "=r"(r[2]), "=r"(r[3]) : "r"(addr));
}
__device__ __forceinline__ void ldsm_x4_t(uint32_t* r, uint32_t addr) {
    asm volatile(
        "ldmatrix.sync.aligned.m8n8.x4.trans.shared.b16 {%0,%1,%2,%3}, [%4];"
        : "=r"(r[0]), "=r"(r[1]), "=r"(r[2]), "=r"(r[3]) : "r"(addr));
}
__device__ __forceinline__ void mma_bf16(float* d, const uint32_t* a,
                                         uint32_t b0, uint32_t b1) {
    asm volatile(
        "mma.sync.aligned.m16n8k16.row.col.f32.bf16.bf16.f32 "
        "{%0,%1,%2,%3}, {%4,%5,%6,%7}, {%8,%9}, {%0,%1,%2,%3};"
        : "+f"(d[0]), "+f"(d[1]), "+f"(d[2]), "+f"(d[3])
        : "r"(a[0]), "r"(a[1]), "r"(a[2]), "r"(a[3]), "r"(b0), "r"(b1));
}

// fast exp: 2^(x*log2e) via round+poly, FMA-only (no MUFU).
__device__ __forceinline__ float fexp(float x) {
    x = fmaxf(x, -88.0f);
    float t  = fmaf(x, 1.4426950408889634f, 12582912.0f);
    float nf = t - 12582912.0f;
    float r  = fmaf(x, 1.4426950408889634f, -nf);
    float p  = 1.3333558146428443e-3f;
    p = fmaf(p, r, 9.6181291076284772e-3f);
    p = fmaf(p, r, 5.5504108664821580e-2f);
    p = fmaf(p, r, 2.4022650695910072e-1f);
    p = fmaf(p, r, 6.9314718055994531e-1f);
    p = fmaf(p, r, 1.0f);
    int n = (int)nf;
    return p * __int_as_float((n + 127) << 23);
}

// split pair of fp32 -> packed bf16x2 hi and lo
__device__ __forceinline__ void split2(float a, float b,
                                       uint32_t& hi, uint32_t& lo) {
    __nv_bfloat16 ha = __float2bfloat16(a), hb = __float2bfloat16(b);
    float ra = a - __bfloat162float(ha);
    float rb = b - __bfloat162float(hb);
    __nv_bfloat162 H = __halves2bfloat162(ha, hb);
    __nv_bfloat162 L = __halves2bfloat162(__float2bfloat16(ra),
                                          __float2bfloat16(rb));
    hi = *(uint32_t*)&H;
    lo = *(uint32_t*)&L;
}

// ---------------------------------------------------------------------------
// Split fp32 -> (hi, lo) bf16 pair.
// ---------------------------------------------------------------------------
__global__ void split_bf16_kernel(const float* __restrict__ x,
                                  __nv_bfloat16* __restrict__ hi,
                                  __nv_bfloat16* __restrict__ lo, int n) {
    int i = blockIdx.x * blockDim.x + threadIdx.x;
    if (i >= n) return;
    float v = x[i];
    __nv_bfloat16 h = __float2bfloat16(v);
    float r = v - __bfloat162float(h);
    hi[i] = h;
    lo[i] = __float2bfloat16(r);
}

// ---------------------------------------------------------------------------
// bf16x3 GEMM via mma.sync: C[m][n] = sum_k A[m][k]*B[n][k] (fp32 out)
// CTA tile 128m x 256n, BK=32, 512 threads = 16 warps (2m x 8n), warp 64x32.
// 4 warps/SMSP for latency hiding. 3-stage cp.async pipeline.
// smem/stage: Ahi 10240 | Alo 10240 | Bhi 20480 | Blo 20480 = 61440 B.
// ---------------------------------------------------------------------------
#define GP 80                       // bytes per smem row (32 bf16 + 8 pad)
#define GA_T (128 * GP)             // 10240
#define GB_T (256 * GP)             // 20480
#define GSTG (2 * GA_T + 2 * GB_T)  // 61440
#define GEMM_SMEM (3 * GSTG)        // 184320

__device__ __forceinline__ void gemm_stage_load(
    uint32_t stg, const __nv_bfloat16* Ahi, const __nv_bfloat16* Alo,
    const __nv_bfloat16* Bhi, const __nv_bfloat16* Blo,
    int K, int k0, int tid)
{
#pragma unroll
    for (int i = 0; i < 6; i++) {
        int c = tid + i * 512;                 // 0..3071 16B chunks
        if (c < 1024) {                        // A: 2 tensors x 512
            int tns = c >> 9, rem = c & 511;
            int row = rem >> 2, ch = rem & 3;
            const __nv_bfloat16* src = tns ? Alo : Ahi;
            cp_async16(stg + tns * GA_T + row * GP + ch * 16,
                       src + (size_t)row * K + k0 + ch * 8);
        } else {                               // B: 2 tensors x 1024
            int cb = c - 1024;
            int tns = cb >> 10, rem = cb & 1023;
            int row = rem >> 2, ch = rem & 3;
            const __nv_bfloat16* src = tns ? Blo : Bhi;
            cp_async16(stg + 2 * GA_T + tns * GB_T + row * GP + ch * 16,
                       src + (size_t)row * K + k0 + ch * 8);
        }
    }
}

__global__ __launch_bounds__(512, 1) void gemm_mma_bf16x3(
    const __nv_bfloat16* __restrict__ Ahi, const __nv_bfloat16* __restrict__ Alo,
    const __nv_bfloat16* __restrict__ Bhi, const __nv_bfloat16* __restrict__ Blo,
    float* __restrict__ C, int M, int N, int K)
{
    extern __shared__ __align__(128) char sm[];
    const uint32_t sbase = smem_u32(sm);

    const int tid = threadIdx.x;
    const int wid = tid >> 5, lane = tid & 31;
    const int wm = wid >> 3, wn = wid & 7;         // 2m x 8n warps
    const int bm = blockIdx.x * 128, bn = blockIdx.y * 256;

    const __nv_bfloat16* Ah = Ahi + (size_t)bm * K;
    const __nv_bfloat16* Al = Alo + (size_t)bm * K;
    const __nv_bfloat16* Bh = Bhi + (size_t)bn * K;
    const __nv_bfloat16* Bl = Blo + (size_t)bn * K;

    float acc[4][4][4];                            // mt(16r) x nt(8c) x frag
#pragma unroll
    for (int mt = 0; mt < 4; mt++)
#pragma unroll
        for (int nt = 0; nt < 4; nt++)
#pragma unroll
            for (int q = 0; q < 4; q++) acc[mt][nt][q] = 0.0f;

    const int nkt = K >> 5;

    // prologue: fill 3 stages
    gemm_stage_load(sbase,            Ah, Al, Bh, Bl, K, 0,  tid); cp_commit();
    gemm_stage_load(sbase + GSTG,     Ah, Al, Bh, Bl, K, 32, tid); cp_commit();
    gemm_stage_load(sbase + 2 * GSTG, Ah, Al, Bh, Bl, K, 64, tid); cp_commit();

    const int lrow = lane & 15;
    const int khalf = (lane >> 4) * 16;

    int stg_idx = 0;
    for (int kt = 0; kt < nkt; kt++) {
        cp_wait<2>();
        __syncthreads();
        const uint32_t stg = sbase + stg_idx * GSTG;
        const uint32_t abase = stg;
        const uint32_t bbase = stg + 2 * GA_T;

#pragma unroll
        for (int ks = 0; ks < 2; ks++) {
            const int kso = ks * 32 + khalf;
            // B fragments: 32 cols = 2 x4 per tensor
            uint32_t bh4[2][4], bl4[2][4];
            const int brow = wn * 32 + lrow;
#pragma unroll
            for (int h = 0; h < 2; h++) {
                uint32_t bd = bbase + (brow + h * 16) * GP + kso;
                ldsm_x4(bh4[h], bd);
                ldsm_x4(bl4[h], bd + GB_T);
            }
            // A fragments: 64 rows = 4 x4 per tensor
            uint32_t ah[4][4], al[4][4];
            const int arow = wm * 64 + lrow;
#pragma unroll
            for (int mt = 0; mt < 4; mt++) {
                uint32_t ad = abase + (arow + mt * 16) * GP + kso;
                ldsm_x4(ah[mt], ad);
                ldsm_x4(al[mt], ad + GA_T);
            }
#pragma unroll
            for (int mt = 0; mt < 4; mt++) {
#pragma unroll
                for (int h = 0; h < 2; h++) {
#pragma unroll
                    for (int s = 0; s < 2; s++) {
                        const int nt = h * 2 + s;
                        mma_bf16(acc[mt][nt], ah[mt], bh4[h][s], bh4[h][s + 2]);
                        mma_bf16(acc[mt][nt], ah[mt], bl4[h][s], bl4[h][s + 2]);
                        mma_bf16(acc[mt][nt], al[mt], bh4[h][s], bh4[h][s + 2]);
                    }
                }
            }
        }

        __syncthreads();
        if (kt + 3 < nkt) {
            gemm_stage_load(stg, Ah, Al, Bh, Bl, K, (kt + 3) * 32, tid);
        }
        cp_commit();
        stg_idx = (stg_idx == 2) ? 0 : stg_idx + 1;
    }

    // epilogue
    const int g4 = lane >> 2, l4 = lane & 3;
#pragma unroll
    for (int mt = 0; mt < 4; mt++) {
        const int r0 = bm + wm * 64 + mt * 16 + g4;
#pragma unroll
        for (int nt = 0; nt < 4; nt++) {
            const int col = bn + wn * 32 + nt * 8 + l4 * 2;
            *(float2*)(C + (size_t)r0 * N + col) =
                make_float2(acc[mt][nt][0], acc[mt][nt][1]);
            *(float2*)(C + (size_t)(r0 + 8) * N + col) =
                make_float2(acc[mt][nt][2], acc[mt][nt][3]);
        }
    }
}

// ---------------------------------------------------------------------------
// Fused RoPE + bf16 hi/lo split of the QKV tensor (unchanged, passing).
// ---------------------------------------------------------------------------
__global__ void rope_split_kernel(const float* __restrict__ cosp,
                                  const float* __restrict__ sinp)
{
    int idx = blockIdx.x * blockDim.x + threadIdx.x;
    const int total = T_SEQ * NG * 6 * 64;
    if (idx >= total) return;
    int i = idx & 63;
    int r = idx >> 6;
    int s = r % 6; r /= 6;
    int g = r & 7;
    int t = r >> 3;

    const size_t off = (size_t)t * QKV_N + g * 768 + s * 128;
    const float* base = g_qkv + off;
    const float sc = (s < 4) ? 0.08838834764831845f : 1.0f;

    int d1, d2;
    float o1, o2;
    if (s < 5 && i < 32) {
        float x1 = base[i], x2 = base[i + 32];
        float c1 = cosp[t * 64 + i],      s1 = sinp[t * 64 + i];
        float c2 = cosp[t * 64 + i + 32], s2 = sinp[t * 64 + i + 32];
        o1 = (x1 * c1 - x2 * s1) * sc;
        o2 = (x2 * c2 + x1 * s2) * sc;
        d1 = i; d2 = i + 32;
    } else if (s < 5) {
        d1 = i + 32; d2 = i + 64;
        o1 = base[d1] * sc; o2 = base[d2] * sc;
    } else {
        d1 = i; d2 = i + 64;
        o1 = base[d1]; o2 = base[d2];
    }
    __nv_bfloat16 h1 = __float2bfloat16(o1);
    __nv_bfloat16 h2 = __float2bfloat16(o2);
    g_qkvh[off + d1] = h1;
    g_qkvh[off + d2] = h2;
    g_qkvl[off + d1] = __float2bfloat16(o1 - __bfloat162float(h1));
    g_qkvl[off + d2] = __float2bfloat16(o2 - __bfloat162float(h2));
}

// ---------------------------------------------------------------------------
// Tensor-core flash attention (bf16x3, causal) — unchanged (passing).
// ---------------------------------------------------------------------------
#define AP   272
#define KVT  (64 * AP)
#define KVBUF (4 * KVT)
#define ATTN_SMEM (2 * KVBUF)

__device__ __forceinline__ void attn_load_kv(
    uint32_t dstbase, const __nv_bfloat16* kh, const __nv_bfloat16* kl,
    const __nv_bfloat16* vh, const __nv_bfloat16* vl, int k0, int tid)
{
    const __nv_bfloat16* srcs[4] = {kh, kl, vh, vl};
#pragma unroll
    for (int it = 0; it < 16; it++) {
        int c = tid + it * 256;
        int tensor = c >> 10;
        int rem = c & 1023;
        int row = rem >> 4, ch = rem & 15;
        cp_async16(dstbase + tensor * KVT + row * AP + ch * 16,
                   srcs[tensor] + (size_t)(k0 + row) * QKV_N + ch * 8);
    }
}

__global__ __launch_bounds__(256, 1) void attn_mma_kernel()
{
    extern __shared__ __align__(128) char sma[];
    const uint32_t sbase = smem_u32(sma);
    const int tid = threadIdx.x;
    const int wid = tid >> 5, lane = tid & 31;

    const int qb = (gridDim.x - 1) - blockIdx.x;
    const int h  = blockIdx.y;
    const int g = h >> 2, s = h & 3;

    const __nv_bfloat16* Qh = g_qkvh + (size_t)(qb * 128) * QKV_N
                            + g * 768 + s * 128;
    const __nv_bfloat16* Ql = g_qkvl + (size_t)(qb * 128) * QKV_N
                            + g * 768 + s * 128;
    const __nv_bfloat16* Kh = g_qkvh + g * 768 + 512;
    const __nv_bfloat16* Kl = g_qkvl + g * 768 + 512;
    const __nv_bfloat16* Vh = g_qkvh + g * 768 + 640;
    const __nv_bfloat16* Vl = g_qkvl + g * 768 + 640;

#pragma unroll
    for (int it = 0; it < 16; it++) {
        int c = tid + it * 256;
        int tensor = c >> 11;
        int rem = c & 2047;
        int row = rem >> 4, ch = rem & 15;
        const __nv_bfloat16* src = (tensor ? Ql : Qh);
        cp_async16(sbase + tensor * (128 * AP) + row * AP + ch * 16,
                   src + (size_t)row * QKV_N + ch * 8);
    }
    cp_commit();
    cp_wait<0>();
    __syncthreads();

    uint32_t qfh[8][4], qfl[8][4];
    {
        uint32_t qa = sbase + (wid * 16 + (lane & 15)) * AP + (lane >> 4) * 16;
#pragma unroll
        for (int ks = 0; ks < 8; ks++) {
            ldsm_x4(qfh[ks], qa + ks * 32);
            ldsm_x4(qfl[ks], qa + 128 * AP + ks * 32);
        }
    }
    __syncthreads();

    const int nt_tiles = 2 * qb + 2;
    attn_load_kv(sbase, Kh, Kl, Vh, Vl, 0, tid);
    cp_commit();
    attn_load_kv(sbase + KVBUF, Kh, Kl, Vh, Vl, 64, tid);
    cp_commit();

    float oacc[16][4];
#pragma unroll
    for (int nt = 0; nt < 16; nt++)
#pragma unroll
        for (int q = 0; q < 4; q++) oacc[nt][q] = 0.0f;
    float m0 = -1e30f, m1 = -1e30f, l0 = 0.0f, l1 = 0.0f;

    const int row0 = qb * 128 + wid * 16 + (lane >> 2);
    const int row1 = row0 + 8;

    for (int kt = 0; kt < nt_tiles; kt++) {
        cp_wait<1>();
        __syncthreads();
        const uint32_t kb = sbase + (kt & 1) * KVBUF;
        const int k0 = kt * 64;

        float sacc[8][4];
#pragma unroll
        for (int nt = 0; nt < 8; nt++)
#pragma unroll
            for (int q = 0; q < 4; q++) sacc[nt][q] = 0.0f;

        const uint32_t kaddr = kb + (lane & 15) * AP + (lane >> 4) * 16;
#pragma unroll
        for (int ks = 0; ks < 8; ks++) {
#pragma unroll
            for (int p = 0; p < 4; p++) {
                uint32_t kh4[4], kl4[4];
                uint32_t a = kaddr + p * 16 * AP + ks * 32;
                ldsm_x4(kh4, a);
                ldsm_x4(kl4, a + KVT);
                mma_bf16(sacc[2 * p],     qfh[ks], kh4[0], kh4[2]);
                mma_bf16(sacc[2 * p],     qfh[ks], kl4[0], kl4[2]);
                mma_bf16(sacc[2 * p],     qfl[ks], kh4[0], kh4[2]);
                mma_bf16(sacc[2 * p + 1], qfh[ks], kh4[1], kh4[3]);
                mma_bf16(sacc[2 * p + 1], qfh[ks], kl4[1], kl4[3]);
                mma_bf16(sacc[2 * p + 1], qfl[ks], kh4[1], kh4[3]);
            }
        }

        if (k0 + 63 > row0) {
#pragma unroll
            for (int nt = 0; nt < 8; nt++) {
                int col = k0 + nt * 8 + 2 * (lane & 3);
                if (col     > row0) sacc[nt][0] = -1e30f;
                if (col + 1 > row0) sacc[nt][1] = -1e30f;
                if (col     > row1) sacc[nt][2] = -1e30f;
                if (col + 1 > row1) sacc[nt][3] = -1e30f;
            }
        }

        float mt0 = -1e30f, mt1 = -1e30f;
#pragma unroll
        for (int nt = 0; nt < 8; nt++) {
            mt0 = fmaxf(mt0, fmaxf(sacc[nt][0], sacc[nt][1]));
            mt1 = fmaxf(mt1, fmaxf(sacc[nt][2], sacc[nt][3]));
        }
        mt0 = fmaxf(mt0, __shfl_xor_sync(0xffffffffu, mt0, 1));
        mt0 = fmaxf(mt0, __shfl_xor_sync(0xffffffffu, mt0, 2));
        mt1 = fmaxf(mt1, __shfl_xor_sync(0xffffffffu, mt1, 1));
        mt1 = fmaxf(mt1, __shfl_xor_sync(0xffffffffu, mt1, 2));

        float mn0 = fmaxf(m0, mt0), mn1 = fmaxf(m1, mt1);
        float c0 = fexp(m0 - mn0), c1 = fexp(m1 - mn1);
        m0 = mn0; m1 = mn1;

        float s0 = 0.0f, s1 = 0.0f;
#pragma unroll
        for (int nt = 0; nt < 8; nt++) {
            sacc[nt][0] = fexp(sacc[nt][0] - m0);
            sacc[nt][1] = fexp(sacc[nt][1] - m0);
            sacc[nt][2] = fexp(sacc[nt][2] - m1);
            sacc[nt][3] = fexp(sacc[nt][3] - m1);
            s0 += sacc[nt][0] + sacc[nt][1];
            s1 += sacc[nt][2] + sacc[nt][3];
        }
        s0 += __shfl_xor_sync(0xffffffffu, s0, 1);
        s0 += __shfl_xor_sync(0xffffffffu, s0, 2);
        s1 += __shfl_xor_sync(0xffffffffu, s1, 1);
        s1 += __shfl_xor_sync(0xffffffffu, s1, 2);
        l0 = l0 * c0 + s0;
        l1 = l1 * c1 + s1;
#pragma unroll
        for (int nt = 0; nt < 16; nt++) {
            oacc[nt][0] *= c0; oacc[nt][1] *= c0;
            oacc[nt][2] *= c1; oacc[nt][3] *= c1;
        }

        const uint32_t vbase = kb + 2 * KVT
            + ((lane & 7) + ((lane >> 3) & 1) * 8) * AP + (lane >> 4) * 16;
#pragma unroll
        for (int kk = 0; kk < 4; kk++) {
            uint32_t pah[4], pal[4];
            split2(sacc[2 * kk][0],     sacc[2 * kk][1],     pah[0], pal[0]);
            split2(sacc[2 * kk][2],     sacc[2 * kk][3],     pah[1], pal[1]);
            split2(sacc[2 * kk + 1][0], sacc[2 * kk + 1][1], pah[2], pal[2]);
            split2(sacc[2 * kk + 1][2], sacc[2 * kk + 1][3], pah[3], pal[3]);
#pragma unroll
            for (int nb = 0; nb < 8; nb++) {
                uint32_t vh4[4], vl4[4];
                uint32_t va = vbase + kk * 16 * AP + nb * 32;
                ldsm_x4_t(vh4, va);
                ldsm_x4_t(vl4, va + KVT);
                mma_bf16(oacc[2 * nb],     pah, vh4[0], vh4[1]);
                mma_bf16(oacc[2 * nb],     pah, vl4[0], vl4[1]);
                mma_bf16(oacc[2 * nb],     pal, vh4[0], vh4[1]);
                mma_bf16(oacc[2 * nb + 1], pah, vh4[2], vh4[3]);
                mma_bf16(oacc[2 * nb + 1], pah, vl4[2], vl4[3]);
                mma_bf16(oacc[2 * nb + 1], pal, vh4[2], vh4[3]);
            }
        }

        __syncthreads();
        if (kt + 2 < nt_tiles)
            attn_load_kv(sbase + (kt & 1) * KVBUF, Kh, Kl, Vh, Vl,
                         (kt + 2) * 64, tid);
        cp_commit();
    }

    const float il0 = 1.0f / l0, il1 = 1.0f / l1;
#pragma unroll
    for (int nt = 0; nt < 16; nt++) {
        float o0 = oacc[nt][0] * il0, o1 = oacc[nt][1] * il0;
        float o2 = oacc[nt][2] * il1, o3 = oacc[nt][3] * il1;
        uint32_t hi0, lo0, hi1, lo1;
        split2(o0, o1, hi0, lo0);
        split2(o2, o3, hi1, lo1);
        size_t off0 = (size_t)row0 * D_EMB + h * DH + nt * 8 + 2 * (lane & 3);
        size_t off1 = (size_t)row1 * D_EMB + h * DH + nt * 8 + 2 * (lane & 3);
        *(uint32_t*)(g_ahi + off0) = hi0;
        *(uint32_t*)(g_alo + off0) = lo0;
        *(uint32_t*)(g_ahi + off1) = hi1;
        *(uint32_t*)(g_alo + off1) = lo1;
    }
}

// ---------------------------------------------------------------------------
// kernel_launch
// ---------------------------------------------------------------------------
extern "C" void kernel_launch(void* const* d_in, const int* in_sizes, int n_in,
                              void* d_out, int out_size)
{
    const float* x    = (const float*)d_in[0];
    const float* Wqkv = (const float*)d_in[1];
    const float* Wout = (const float*)d_in[2];
    const float* cosp = (const float*)d_in[3];
    const float* sinp = (const float*)d_in[4];
    float* out = (float*)d_out;

    float* qkv = nullptr;
    __nv_bfloat16 *ahi, *alo, *whi, *wlo;
    cudaGetSymbolAddress((void**)&qkv, g_qkv);
    cudaGetSymbolAddress((void**)&ahi, g_ahi);
    cudaGetSymbolAddress((void**)&alo, g_alo);
    cudaGetSymbolAddress((void**)&whi, g_whi);
    cudaGetSymbolAddress((void**)&wlo, g_wlo);

    cudaFuncSetAttribute(gemm_mma_bf16x3,
                         cudaFuncAttributeMaxDynamicSharedMemorySize,
                         GEMM_SMEM);
    cudaFuncSetAttribute(attn_mma_kernel,
                         cudaFuncAttributeMaxDynamicSharedMemorySize,
                         ATTN_SMEM);

    // 1) split x and Wqkv
    {
        int n = T_SEQ * D_EMB;
        split_bf16_kernel<<<(n + 255) / 256, 256>>>(x, ahi, alo, n);
        int m = QKV_N * D_EMB;
        split_bf16_kernel<<<(m + 255) / 256, 256>>>(Wqkv, whi, wlo, m);
    }
    // 2) QKV projection (tensor cores) -> fp32 qkv
    gemm_mma_bf16x3<<<dim3(T_SEQ / 128, QKV_N / 256), 512, GEMM_SMEM>>>(
        ahi, alo, whi, wlo, qkv, T_SEQ, QKV_N, D_EMB);
    // 3) fused RoPE + bf16 hi/lo split
    {
        int total = T_SEQ * NG * 6 * 64;
        rope_split_kernel<<<(total + 255) / 256, 256>>>(cosp, sinp);
    }
    // 4) tensor-core flash attention -> y hi/lo (g_ahi/g_alo)
    attn_mma_kernel<<<dim3(T_SEQ / 128, NH), 256, ATTN_SMEM>>>();
    // 5) split Wout, then output projection
    {
        int m = D_EMB * D_EMB;
        split_bf16_kernel<<<(m + 255) / 256, 256>>>(Wout, whi, wlo, m);
    }
    gemm_mma_bf16x3<<<dim3(T_SEQ / 128, D_EMB / 256), 512, GEMM_SMEM>>>(
        ahi, alo, whi, wlo, out, T_SEQ, D_EMB, D_EMB);
}

// round 7
// speedup vs baseline: 1.4906x; 1.4906x over previous
#include <cuda_runtime.h>
#include <cuda_bf16.h>
#include <cstdint>
#include <math.h>

#define T_SEQ 2048
#define D_EMB 4096
#define QKV_N 6144
#define NH 32
#define DH 128
#define NG 8

// ---------------------------------------------------------------------------
// Scratch (__device__ globals; no cudaMalloc allowed)
// ---------------------------------------------------------------------------
__device__ float g_qkv[T_SEQ * QKV_N];              // fp32 QKV (gemm1 out)
__device__ float g_y[T_SEQ * D_EMB];                // fp32 attention out
__device__ __nv_bfloat16 g_qkvh[T_SEQ * QKV_N];     // roped+split QKV hi
__device__ __nv_bfloat16 g_qkvl[T_SEQ * QKV_N];     // roped+split QKV lo

// ---------------------------------------------------------------------------
// helpers
// ---------------------------------------------------------------------------
__device__ __forceinline__ uint32_t smem_u32(const void* p) {
    uint32_t a;
    asm("{ .reg .u64 t; cvta.to.shared.u64 t, %1; cvt.u32.u64 %0, t; }"
        : "=r"(a) : "l"(p));
    return a;
}
__device__ __forceinline__ void cp_async16(uint32_t dst, const void* src) {
    asm volatile("cp.async.cg.shared.global [%0], [%1], 16;"
                 :: "r"(dst), "l"(src));
}
__device__ __forceinline__ void cp_commit() {
    asm volatile("cp.async.commit_group;");
}
template <int N>
__device__ __forceinline__ void cp_wait() {
    asm volatile("cp.async.wait_group %0;" :: "n"(N));
}
__device__ __forceinline__ void ldsm_x4(uint32_t* r, uint32_t addr) {
    asm volatile("ldmatrix.sync.aligned.m8n8.x4.shared.b16 {%0,%1,%2,%3}, [%4];"
                 : "=r"(r[0]), "=r"(r[1]), "=r"(r[2]), "=r"(r[3]) : "r"(addr));
}
__device__ __forceinline__ void ldsm_x4_t(uint32_t* r, uint32_t addr) {
    asm volatile(
        "ldmatrix.sync.aligned.m8n8.x4.trans.shared.b16 {%0,%1,%2,%3}, [%4];"
        : "=r"(r[0]), "=r"(r[1]), "=r"(r[2]), "=r"(r[3]) : "r"(addr));
}
__device__ __forceinline__ void mma_bf16(float* d, const uint32_t* a,
                                         uint32_t b0, uint32_t b1) {
    asm volatile(
        "mma.sync.aligned.m16n8k16.row.col.f32.bf16.bf16.f32 "
        "{%0,%1,%2,%3}, {%4,%5,%6,%7}, {%8,%9}, {%0,%1,%2,%3};"
        : "+f"(d[0]), "+f"(d[1]), "+f"(d[2]), "+f"(d[3])
        : "r"(a[0]), "r"(a[1]), "r"(a[2]), "r"(a[3]), "r"(b0), "r"(b1));
}
__device__ __forceinline__ void mma_tf32(float* d, const uint32_t* a,
                                         uint32_t b0, uint32_t b1) {
    asm volatile(
        "mma.sync.aligned.m16n8k8.row.col.f32.tf32.tf32.f32 "
        "{%0,%1,%2,%3}, {%4,%5,%6,%7}, {%8,%9}, {%0,%1,%2,%3};"
        : "+f"(d[0]), "+f"(d[1]), "+f"(d[2]), "+f"(d[3])
        : "r"(a[0]), "r"(a[1]), "r"(a[2]), "r"(a[3]), "r"(b0), "r"(b1));
}
__device__ __forceinline__ uint32_t cvt_tf32(float x) {
    uint32_t r;
    asm("cvt.rna.tf32.f32 %0, %1;" : "=r"(r) : "f"(x));
    return r;
}

// fast exp: 2^(x*log2e) via round+poly, FMA-only (no MUFU).
__device__ __forceinline__ float fexp(float x) {
    x = fmaxf(x, -88.0f);
    float t  = fmaf(x, 1.4426950408889634f, 12582912.0f);
    float nf = t - 12582912.0f;
    float r  = fmaf(x, 1.4426950408889634f, -nf);
    float p  = 1.3333558146428443e-3f;
    p = fmaf(p, r, 9.6181291076284772e-3f);
    p = fmaf(p, r, 5.5504108664821580e-2f);
    p = fmaf(p, r, 2.4022650695910072e-1f);
    p = fmaf(p, r, 6.9314718055994531e-1f);
    p = fmaf(p, r, 1.0f);
    int n = (int)nf;
    return p * __int_as_float((n + 127) << 23);
}

// split pair of fp32 -> packed bf16x2 hi and lo
__device__ __forceinline__ void split2(float a, float b,
                                       uint32_t& hi, uint32_t& lo) {
    __nv_bfloat16 ha = __float2bfloat16(a), hb = __float2bfloat16(b);
    float ra = a - __bfloat162float(ha);
    float rb = b - __bfloat162float(hb);
    __nv_bfloat162 H = __halves2bfloat162(ha, hb);
    __nv_bfloat162 L = __halves2bfloat162(__float2bfloat16(ra),
                                          __float2bfloat16(rb));
    hi = *(uint32_t*)&H;
    lo = *(uint32_t*)&L;
}

// ---------------------------------------------------------------------------
// Single-pass tf32 GEMM via mma.sync.m16n8k8:
//   C[m][n] = sum_k A[m][k] * B[n][k]   (A,B fp32 K-major, C fp32)
// CTA tile 128m x 256n, BK=32, 256 threads = 8 warps (2m x 4n), warp 64x64.
// 3-stage cp.async pipeline. smem rows padded to 36 floats (144B):
// fragment LDS word index = 4*row + col (mod 32) -> conflict-free.
// ---------------------------------------------------------------------------
#define TP 144                        // bytes per smem row (32 f32 + 4 pad)
#define TA_SZ (128 * TP)              // 18432
#define TB_SZ (256 * TP)              // 36864
#define TSTG (TA_SZ + TB_SZ)          // 55296
#define TGEMM_SMEM (3 * TSTG)         // 165888

__device__ __forceinline__ void tf32_stage_load(
    uint32_t stg, const float* A, const float* B, int K, int k0, int tid)
{
#pragma unroll
    for (int i = 0; i < 12; i++) {
        int c = tid + i * 256;                 // 0..3071 16B chunks
        if (c < 1024) {                        // A: 128 rows x 8 chunks
            int row = c >> 3, ch = c & 7;
            cp_async16(stg + row * TP + ch * 16,
                       A + (size_t)row * K + k0 + ch * 4);
        } else {                               // B: 256 rows x 8 chunks
            int cb = c - 1024;
            int row = cb >> 3, ch = cb & 7;
            cp_async16(stg + TA_SZ + row * TP + ch * 16,
                       B + (size_t)row * K + k0 + ch * 4);
        }
    }
}

__global__ __launch_bounds__(256, 1) void gemm_tf32(
    const float* __restrict__ A, const float* __restrict__ B,
    float* __restrict__ C, int M, int N, int K)
{
    extern __shared__ __align__(128) char sm[];
    const uint32_t sbase = smem_u32(sm);

    const int tid = threadIdx.x;
    const int wid = tid >> 5, lane = tid & 31;
    const int wm = wid >> 2, wn = wid & 3;         // 2m x 4n warps
    const int bm = blockIdx.x * 128, bn = blockIdx.y * 256;

    const float* Ab = A + (size_t)bm * K;
    const float* Bb = B + (size_t)bn * K;

    float acc[4][8][4];
#pragma unroll
    for (int mt = 0; mt < 4; mt++)
#pragma unroll
        for (int nt = 0; nt < 8; nt++)
#pragma unroll
            for (int q = 0; q < 4; q++) acc[mt][nt][q] = 0.0f;

    const int nkt = K >> 5;

    tf32_stage_load(sbase,            Ab, Bb, K, 0,  tid); cp_commit();
    tf32_stage_load(sbase + TSTG,     Ab, Bb, K, 32, tid); cp_commit();
    tf32_stage_load(sbase + 2 * TSTG, Ab, Bb, K, 64, tid); cp_commit();

    const int g = lane >> 2, c = lane & 3;

    int stg_idx = 0;
    for (int kt = 0; kt < nkt; kt++) {
        cp_wait<2>();
        __syncthreads();
        const uint32_t stg = sbase + stg_idx * TSTG;

#pragma unroll
        for (int ks = 0; ks < 4; ks++) {
            const int kb = (ks * 8 + c) * 4;       // byte offset of col
            // B fragments: 8 n-tiles x 2 regs
            uint32_t bf[8][2];
            const int brow = wn * 64 + g;
#pragma unroll
            for (int nt = 0; nt < 8; nt++) {
                uint32_t bd = stg + TA_SZ + (brow + nt * 8) * TP + kb;
                bf[nt][0] = cvt_tf32(*(const float*)(sm + (bd - sbase)));
                bf[nt][1] = cvt_tf32(*(const float*)(sm + (bd - sbase) + 16));
            }
            // A fragments: 4 m-tiles x 4 regs
            uint32_t af[4][4];
            const int arow = wm * 64 + g;
#pragma unroll
            for (int mt = 0; mt < 4; mt++) {
                uint32_t ad = stg + (arow + mt * 16) * TP + kb - sbase;
                af[mt][0] = cvt_tf32(*(const float*)(sm + ad));
                af[mt][1] = cvt_tf32(*(const float*)(sm + ad + 8 * TP));
                af[mt][2] = cvt_tf32(*(const float*)(sm + ad + 16));
                af[mt][3] = cvt_tf32(*(const float*)(sm + ad + 8 * TP + 16));
            }
#pragma unroll
            for (int mt = 0; mt < 4; mt++)
#pragma unroll
                for (int nt = 0; nt < 8; nt++)
                    mma_tf32(acc[mt][nt], af[mt], bf[nt][0], bf[nt][1]);
        }

        __syncthreads();
        if (kt + 3 < nkt) {
            tf32_stage_load(stg, Ab, Bb, K, (kt + 3) * 32, tid);
        }
        cp_commit();
        stg_idx = (stg_idx == 2) ? 0 : stg_idx + 1;
    }

    // epilogue
    const int l4 = lane & 3;
#pragma unroll
    for (int mt = 0; mt < 4; mt++) {
        const int r0 = bm + wm * 64 + mt * 16 + g;
#pragma unroll
        for (int nt = 0; nt < 8; nt++) {
            const int col = bn + wn * 64 + nt * 8 + l4 * 2;
            *(float2*)(C + (size_t)r0 * N + col) =
                make_float2(acc[mt][nt][0], acc[mt][nt][1]);
            *(float2*)(C + (size_t)(r0 + 8) * N + col) =
                make_float2(acc[mt][nt][2], acc[mt][nt][3]);
        }
    }
}

// ---------------------------------------------------------------------------
// Fused RoPE + bf16 hi/lo split of the QKV tensor (unchanged, passing).
// ---------------------------------------------------------------------------
__global__ void rope_split_kernel(const float* __restrict__ cosp,
                                  const float* __restrict__ sinp)
{
    int idx = blockIdx.x * blockDim.x + threadIdx.x;
    const int total = T_SEQ * NG * 6 * 64;
    if (idx >= total) return;
    int i = idx & 63;
    int r = idx >> 6;
    int s = r % 6; r /= 6;
    int g = r & 7;
    int t = r >> 3;

    const size_t off = (size_t)t * QKV_N + g * 768 + s * 128;
    const float* base = g_qkv + off;
    const float sc = (s < 4) ? 0.08838834764831845f : 1.0f;

    int d1, d2;
    float o1, o2;
    if (s < 5 && i < 32) {
        float x1 = base[i], x2 = base[i + 32];
        float c1 = cosp[t * 64 + i],      s1 = sinp[t * 64 + i];
        float c2 = cosp[t * 64 + i + 32], s2 = sinp[t * 64 + i + 32];
        o1 = (x1 * c1 - x2 * s1) * sc;
        o2 = (x2 * c2 + x1 * s2) * sc;
        d1 = i; d2 = i + 32;
    } else if (s < 5) {
        d1 = i + 32; d2 = i + 64;
        o1 = base[d1] * sc; o2 = base[d2] * sc;
    } else {
        d1 = i; d2 = i + 64;
        o1 = base[d1]; o2 = base[d2];
    }
    __nv_bfloat16 h1 = __float2bfloat16(o1);
    __nv_bfloat16 h2 = __float2bfloat16(o2);
    g_qkvh[off + d1] = h1;
    g_qkvh[off + d2] = h2;
    g_qkvl[off + d1] = __float2bfloat16(o1 - __bfloat162float(h1));
    g_qkvl[off + d2] = __float2bfloat16(o2 - __bfloat162float(h2));
}

// ---------------------------------------------------------------------------
// Tensor-core flash attention (bf16x3, causal) — epilogue now writes fp32 y.
// ---------------------------------------------------------------------------
#define AP   272
#define KVT  (64 * AP)
#define KVBUF (4 * KVT)
#define ATTN_SMEM (2 * KVBUF)

__device__ __forceinline__ void attn_load_kv(
    uint32_t dstbase, const __nv_bfloat16* kh, const __nv_bfloat16* kl,
    const __nv_bfloat16* vh, const __nv_bfloat16* vl, int k0, int tid)
{
    const __nv_bfloat16* srcs[4] = {kh, kl, vh, vl};
#pragma unroll
    for (int it = 0; it < 16; it++) {
        int c = tid + it * 256;
        int tensor = c >> 10;
        int rem = c & 1023;
        int row = rem >> 4, ch = rem & 15;
        cp_async16(dstbase + tensor * KVT + row * AP + ch * 16,
                   srcs[tensor] + (size_t)(k0 + row) * QKV_N + ch * 8);
    }
}

__global__ __launch_bounds__(256, 1) void attn_mma_kernel()
{
    extern __shared__ __align__(128) char sma[];
    const uint32_t sbase = smem_u32(sma);
    const int tid = threadIdx.x;
    const int wid = tid >> 5, lane = tid & 31;

    const int qb = (gridDim.x - 1) - blockIdx.x;
    const int h  = blockIdx.y;
    const int g = h >> 2, s = h & 3;

    const __nv_bfloat16* Qh = g_qkvh + (size_t)(qb * 128) * QKV_N
                            + g * 768 + s * 128;
    const __nv_bfloat16* Ql = g_qkvl + (size_t)(qb * 128) * QKV_N
                            + g * 768 + s * 128;
    const __nv_bfloat16* Kh = g_qkvh + g * 768 + 512;
    const __nv_bfloat16* Kl = g_qkvl + g * 768 + 512;
    const __nv_bfloat16* Vh = g_qkvh + g * 768 + 640;
    const __nv_bfloat16* Vl = g_qkvl + g * 768 + 640;

#pragma unroll
    for (int it = 0; it < 16; it++) {
        int c = tid + it * 256;
        int tensor = c >> 11;
        int rem = c & 2047;
        int row = rem >> 4, ch = rem & 15;
        const __nv_bfloat16* src = (tensor ? Ql : Qh);
        cp_async16(sbase + tensor * (128 * AP) + row * AP + ch * 16,
                   src + (size_t)row * QKV_N + ch * 8);
    }
    cp_commit();
    cp_wait<0>();
    __syncthreads();

    uint32_t qfh[8][4], qfl[8][4];
    {
        uint32_t qa = sbase + (wid * 16 + (lane & 15)) * AP + (lane >> 4) * 16;
#pragma unroll
        for (int ks = 0; ks < 8; ks++) {
            ldsm_x4(qfh[ks], qa + ks * 32);
            ldsm_x4(qfl[ks], qa + 128 * AP + ks * 32);
        }
    }
    __syncthreads();

    const int nt_tiles = 2 * qb + 2;
    attn_load_kv(sbase, Kh, Kl, Vh, Vl, 0, tid);
    cp_commit();
    attn_load_kv(sbase + KVBUF, Kh, Kl, Vh, Vl, 64, tid);
    cp_commit();

    float oacc[16][4];
#pragma unroll
    for (int nt = 0; nt < 16; nt++)
#pragma unroll
        for (int q = 0; q < 4; q++) oacc[nt][q] = 0.0f;
    float m0 = -1e30f, m1 = -1e30f, l0 = 0.0f, l1 = 0.0f;

    const int row0 = qb * 128 + wid * 16 + (lane >> 2);
    const int row1 = row0 + 8;

    for (int kt = 0; kt < nt_tiles; kt++) {
        cp_wait<1>();
        __syncthreads();
        const uint32_t kb = sbase + (kt & 1) * KVBUF;
        const int k0 = kt * 64;

        float sacc[8][4];
#pragma unroll
        for (int nt = 0; nt < 8; nt++)
#pragma unroll
            for (int q = 0; q < 4; q++) sacc[nt][q] = 0.0f;

        const uint32_t kaddr = kb + (lane & 15) * AP + (lane >> 4) * 16;
#pragma unroll
        for (int ks = 0; ks < 8; ks++) {
#pragma unroll
            for (int p = 0; p < 4; p++) {
                uint32_t kh4[4], kl4[4];
                uint32_t a = kaddr + p * 16 * AP + ks * 32;
                ldsm_x4(kh4, a);
                ldsm_x4(kl4, a + KVT);
                mma_bf16(sacc[2 * p],     qfh[ks], kh4[0], kh4[2]);
                mma_bf16(sacc[2 * p],     qfh[ks], kl4[0], kl4[2]);
                mma_bf16(sacc[2 * p],     qfl[ks], kh4[0], kh4[2]);
                mma_bf16(sacc[2 * p + 1], qfh[ks], kh4[1], kh4[3]);
                mma_bf16(sacc[2 * p + 1], qfh[ks], kl4[1], kl4[3]);
                mma_bf16(sacc[2 * p + 1], qfl[ks], kh4[1], kh4[3]);
            }
        }

        if (k0 + 63 > row0) {
#pragma unroll
            for (int nt = 0; nt < 8; nt++) {
                int col = k0 + nt * 8 + 2 * (lane & 3);
                if (col     > row0) sacc[nt][0] = -1e30f;
                if (col + 1 > row0) sacc[nt][1] = -1e30f;
                if (col     > row1) sacc[nt][2] = -1e30f;
                if (col + 1 > row1) sacc[nt][3] = -1e30f;
            }
        }

        float mt0 = -1e30f, mt1 = -1e30f;
#pragma unroll
        for (int nt = 0; nt < 8; nt++) {
            mt0 = fmaxf(mt0, fmaxf(sacc[nt][0], sacc[nt][1]));
            mt1 = fmaxf(mt1, fmaxf(sacc[nt][2], sacc[nt][3]));
        }
        mt0 = fmaxf(mt0, __shfl_xor_sync(0xffffffffu, mt0, 1));
        mt0 = fmaxf(mt0, __shfl_xor_sync(0xffffffffu, mt0, 2));
        mt1 = fmaxf(mt1, __shfl_xor_sync(0xffffffffu, mt1, 1));
        mt1 = fmaxf(mt1, __shfl_xor_sync(0xffffffffu, mt1, 2));

        float mn0 = fmaxf(m0, mt0), mn1 = fmaxf(m1, mt1);
        float c0 = fexp(m0 - mn0), c1 = fexp(m1 - mn1);
        m0 = mn0; m1 = mn1;

        float s0 = 0.0f, s1 = 0.0f;
#pragma unroll
        for (int nt = 0; nt < 8; nt++) {
            sacc[nt][0] = fexp(sacc[nt][0] - m0);
            sacc[nt][1] = fexp(sacc[nt][1] - m0);
            sacc[nt][2] = fexp(sacc[nt][2] - m1);
            sacc[nt][3] = fexp(sacc[nt][3] - m1);
            s0 += sacc[nt][0] + sacc[nt][1];
            s1 += sacc[nt][2] + sacc[nt][3];
        }
        s0 += __shfl_xor_sync(0xffffffffu, s0, 1);
        s0 += __shfl_xor_sync(0xffffffffu, s0, 2);
        s1 += __shfl_xor_sync(0xffffffffu, s1, 1);
        s1 += __shfl_xor_sync(0xffffffffu, s1, 2);
        l0 = l0 * c0 + s0;
        l1 = l1 * c1 + s1;
#pragma unroll
        for (int nt = 0; nt < 16; nt++) {
            oacc[nt][0] *= c0; oacc[nt][1] *= c0;
            oacc[nt][2] *= c1; oacc[nt][3] *= c1;
        }

        const uint32_t vbase = kb + 2 * KVT
            + ((lane & 7) + ((lane >> 3) & 1) * 8) * AP + (lane >> 4) * 16;
#pragma unroll
        for (int kk = 0; kk < 4; kk++) {
            uint32_t pah[4], pal[4];
            split2(sacc[2 * kk][0],     sacc[2 * kk][1],     pah[0], pal[0]);
            split2(sacc[2 * kk][2],     sacc[2 * kk][3],     pah[1], pal[1]);
            split2(sacc[2 * kk + 1][0], sacc[2 * kk + 1][1], pah[2], pal[2]);
            split2(sacc[2 * kk + 1][2], sacc[2 * kk + 1][3], pah[3], pal[3]);
#pragma unroll
            for (int nb = 0; nb < 8; nb++) {
                uint32_t vh4[4], vl4[4];
                uint32_t va = vbase + kk * 16 * AP + nb * 32;
                ldsm_x4_t(vh4, va);
                ldsm_x4_t(vl4, va + KVT);
                mma_bf16(oacc[2 * nb],     pah, vh4[0], vh4[1]);
                mma_bf16(oacc[2 * nb],     pah, vl4[0], vl4[1]);
                mma_bf16(oacc[2 * nb],     pal, vh4[0], vh4[1]);
                mma_bf16(oacc[2 * nb + 1], pah, vh4[2], vh4[3]);
                mma_bf16(oacc[2 * nb + 1], pah, vl4[2], vl4[3]);
                mma_bf16(oacc[2 * nb + 1], pal, vh4[2], vh4[3]);
            }
        }

        __syncthreads();
        if (kt + 2 < nt_tiles)
            attn_load_kv(sbase + (kt & 1) * KVBUF, Kh, Kl, Vh, Vl,
                         (kt + 2) * 64, tid);
        cp_commit();
    }

    // epilogue: y = O / l (fp32, read by tf32 out-projection)
    const float il0 = 1.0f / l0, il1 = 1.0f / l1;
#pragma unroll
    for (int nt = 0; nt < 16; nt++) {
        size_t off0 = (size_t)row0 * D_EMB + h * DH + nt * 8 + 2 * (lane & 3);
        size_t off1 = (size_t)row1 * D_EMB + h * DH + nt * 8 + 2 * (lane & 3);
        *(float2*)(g_y + off0) =
            make_float2(oacc[nt][0] * il0, oacc[nt][1] * il0);
        *(float2*)(g_y + off1) =
            make_float2(oacc[nt][2] * il1, oacc[nt][3] * il1);
    }
}

// ---------------------------------------------------------------------------
// kernel_launch
// ---------------------------------------------------------------------------
extern "C" void kernel_launch(void* const* d_in, const int* in_sizes, int n_in,
                              void* d_out, int out_size)
{
    const float* x    = (const float*)d_in[0];
    const float* Wqkv = (const float*)d_in[1];
    const float* Wout = (const float*)d_in[2];
    const float* cosp = (const float*)d_in[3];
    const float* sinp = (const float*)d_in[4];
    float* out = (float*)d_out;

    float *qkv = nullptr, *y = nullptr;
    cudaGetSymbolAddress((void**)&qkv, g_qkv);
    cudaGetSymbolAddress((void**)&y, g_y);

    cudaFuncSetAttribute(gemm_tf32,
                         cudaFuncAttributeMaxDynamicSharedMemorySize,
                         TGEMM_SMEM);
    cudaFuncSetAttribute(attn_mma_kernel,
                         cudaFuncAttributeMaxDynamicSharedMemorySize,
                         ATTN_SMEM);

    // 1) QKV projection (tf32 tensor cores): qkv = x @ Wqkv^T
    gemm_tf32<<<dim3(T_SEQ / 128, QKV_N / 256), 256, TGEMM_SMEM>>>(
        x, Wqkv, qkv, T_SEQ, QKV_N, D_EMB);
    // 2) fused RoPE + bf16 hi/lo split
    {
        int total = T_SEQ * NG * 6 * 64;
        rope_split_kernel<<<(total + 255) / 256, 256>>>(cosp, sinp);
    }
    // 3) tensor-core flash attention -> fp32 y
    attn_mma_kernel<<<dim3(T_SEQ / 128, NH), 256, ATTN_SMEM>>>();
    // 4) output projection (tf32): out = y @ Wout^T
    gemm_tf32<<<dim3(T_SEQ / 128, D_EMB / 256), 256, TGEMM_SMEM>>>(
        y, Wout, out, T_SEQ, D_EMB, D_EMB);
}